// round 16
// baseline (speedup 1.0000x reference)
#include <cuda_runtime.h>
#include <cuda_fp16.h>
#include <math.h>
#include <stdint.h>

typedef unsigned long long ull;

// Problem constants (fixed by the dataset)
#define B_DIM 16
#define N_DIM 8192
#define D_DIM 256
#define K_DIM 1024
#define R_TOTAL (B_DIM * N_DIM)     // 131072 rows

// GEMM tiling: 128x128 CTA tile, 8 warps of 64x32, K chunks of 64 fp16
#define BMT 128
#define BNT 128
#define NCHUNK 4                    // single-term fp16: K=256 = 4 chunks of 64
#define NSTAGE 3
#define A_STAGE 16384               // 128 rows * 128 B
#define B_STAGE 16384
#define STAGE_BYTES (A_STAGE + B_STAGE)
#define SMEM_DYN (NSTAGE * STAGE_BYTES)   // 98304 bytes
#define CLUSTER_X 8                 // 8 col-CTAs cover the full K=1024 row

// Scratch (static device globals — no runtime allocation allowed)
__device__ __half g_xh[(size_t)R_TOTAL * D_DIM];
__device__ __half g_ch[(size_t)K_DIM * D_DIM];
__device__ float g_x2[R_TOTAL];
__device__ float g_c2[K_DIM];
__device__ float g_row_partial[R_TOTAL];

// ---------------------------------------------------------------------------
// Helpers. sm_80/sm_90 baseline features only: the harness builds PTX at
// target sm_103 (plain, no 'a' suffix), which accepts mma.sync / cp.async /
// cluster / DSMEM but rejects all tcgen05+TMEM. Verified rounds 5-14.
// ---------------------------------------------------------------------------
__device__ __forceinline__ uint32_t smem_u32(const void* p) {
    uint32_t a;
    asm("{ .reg .u64 t; cvta.to.shared.u64 t, %1; cvt.u32.u64 %0, t; }"
        : "=r"(a) : "l"(p));
    return a;
}
#define SWZ128(o) ((o) ^ (((o) >> 3) & 0x70))

__device__ __forceinline__ void cp_async16(uint32_t dst, const void* src) {
    asm volatile("cp.async.cg.shared.global [%0], [%1], 16;"
                 :: "r"(dst), "l"(src));
}
#define CP_COMMIT()  asm volatile("cp.async.commit_group;")
#define CP_WAIT_1()  asm volatile("cp.async.wait_group 1;")
#define CP_WAIT_0()  asm volatile("cp.async.wait_group 0;")

__device__ __forceinline__ void ldsm_x4(uint32_t& r0, uint32_t& r1,
                                        uint32_t& r2, uint32_t& r3,
                                        uint32_t addr) {
    asm volatile("ldmatrix.sync.aligned.m8n8.x4.shared.b16 {%0,%1,%2,%3}, [%4];"
                 : "=r"(r0), "=r"(r1), "=r"(r2), "=r"(r3) : "r"(addr));
}

__device__ __forceinline__ void mma_16816(float* c, const uint32_t* a,
                                          const uint32_t* b) {
    asm volatile(
        "mma.sync.aligned.m16n8k16.row.col.f32.f16.f16.f32 "
        "{%0,%1,%2,%3}, {%4,%5,%6,%7}, {%8,%9}, {%0,%1,%2,%3};"
        : "+f"(c[0]), "+f"(c[1]), "+f"(c[2]), "+f"(c[3])
        : "r"(a[0]), "r"(a[1]), "r"(a[2]), "r"(a[3]), "r"(b[0]), "r"(b[1]));
}

// --- cluster / DSMEM primitives (sm_90 baseline) ---
__device__ __forceinline__ uint32_t cluster_rank() {
    uint32_t r;
    asm("mov.u32 %0, %%cluster_ctarank;" : "=r"(r));
    return r;
}
__device__ __forceinline__ uint32_t mapa_u32(uint32_t addr, uint32_t rank) {
    uint32_t r;
    asm("mapa.shared::cluster.u32 %0, %1, %2;" : "=r"(r) : "r"(addr), "r"(rank));
    return r;
}
__device__ __forceinline__ float2 ld_dsmem_f2(uint32_t addr) {
    float2 v;
    asm volatile("ld.shared::cluster.v2.f32 {%0,%1}, [%2];"
                 : "=f"(v.x), "=f"(v.y) : "r"(addr));
    return v;
}
#define CLUSTER_ARRIVE() asm volatile("barrier.cluster.arrive.aligned;" ::: "memory")
#define CLUSTER_WAIT()   asm volatile("barrier.cluster.wait.aligned;" ::: "memory")

// ---------------------------------------------------------------------------
// Kernel 1: fp16 convert + fp32 squared norms. One warp per row.
// ---------------------------------------------------------------------------
__global__ __launch_bounds__(256) void prepack_kernel(const float* __restrict__ X,
                                                      const float* __restrict__ C) {
    const int warp_id = (blockIdx.x * blockDim.x + threadIdx.x) >> 5;
    const int lane = threadIdx.x & 31;
    if (warp_id >= R_TOTAL + K_DIM) return;

    const float* src;
    __half* dst;
    float* nrm;
    long r;
    if (warp_id < R_TOTAL) { src = X; dst = g_xh; nrm = g_x2; r = warp_id; }
    else { src = C; dst = g_ch; nrm = g_c2; r = warp_id - R_TOTAL; }

    const float4* p = reinterpret_cast<const float4*>(src + r * D_DIM);
    float4 va = p[lane * 2];
    float4 vb = p[lane * 2 + 1];
    float v[8] = {va.x, va.y, va.z, va.w, vb.x, vb.y, vb.z, vb.w};

    union { __half h[8]; uint4 u; } hv;
    float acc = 0.0f;
    #pragma unroll
    for (int i = 0; i < 8; i++) {
        acc = fmaf(v[i], v[i], acc);
        hv.h[i] = __float2half_rn(v[i]);
    }
    #pragma unroll
    for (int off = 16; off > 0; off >>= 1)
        acc += __shfl_xor_sync(0xFFFFFFFFu, acc, off);
    if (lane == 0) nrm[r] = acc;

    *reinterpret_cast<uint4*>(dst + r * D_DIM + lane * 8) = hv.u;
}

// ---------------------------------------------------------------------------
// Kernel 2: fused sqdist + softmax + loss-partials.
// GEMM (HMMA fp16, K=256) -> epilogue computes e = exp(-dist) in registers,
// reduces per-row (sum e, sum e*sq) CTA-locally, exchanges partials across
// the 8-CTA cluster via DSMEM, writes normalized soft directly. The 1.07 GB
// sq-scratch round-trip of the two-pass version is eliminated.
// ---------------------------------------------------------------------------
__device__ __forceinline__ void load_stage(uint32_t a_s, uint32_t b_s,
                                           int rowBase, int colBase,
                                           int koff, int tid) {
    #pragma unroll
    for (int it = 0; it < 4; it++) {         // A tile: 128 rows x 8 x 16B
        int idx = it * 256 + tid;
        int row = idx >> 3, j = idx & 7;
        cp_async16(a_s + SWZ128(row * 128 + j * 16),
                   g_xh + (size_t)(rowBase + row) * D_DIM + koff + j * 8);
    }
    #pragma unroll
    for (int it = 0; it < 4; it++) {         // B tile: 128 rows x 8 x 16B
        int idx = it * 256 + tid;
        int row = idx >> 3, j = idx & 7;
        cp_async16(b_s + SWZ128(row * 128 + j * 16),
                   g_ch + (size_t)(colBase + row) * D_DIM + koff + j * 8);
    }
}

__global__ __launch_bounds__(256, 2) __cluster_dims__(CLUSTER_X, 1, 1)
void fused_kernel(float* __restrict__ out) {
    extern __shared__ char smem[];
    __shared__ float2 srow[BMT];   // CTA-local  (sum e, sum e*sq) per row
    __shared__ float2 stot[BMT];   // cluster-total per row

    const uint32_t sbase = smem_u32(smem);
    const int tid = threadIdx.x;
    const int wid = tid >> 5;
    const int lane = tid & 31;
    const int rowBase = blockIdx.y * BMT;
    const int colBase = blockIdx.x * BNT;
    const int warp_m = (wid >> 2) * 64;   // 0 or 64
    const int warp_n = (wid & 3) * 32;    // 0,32,64,96
    const uint32_t rank = cluster_rank();

    if (tid < BMT) srow[tid] = make_float2(0.0f, 0.0f);

    uint32_t a_s[NSTAGE], b_s[NSTAGE];
    #pragma unroll
    for (int s = 0; s < NSTAGE; s++) {
        a_s[s] = sbase + s * STAGE_BYTES;
        b_s[s] = a_s[s] + A_STAGE;
    }

    float acc[4][4][4];
    #pragma unroll
    for (int mt = 0; mt < 4; mt++)
        #pragma unroll
        for (int nt = 0; nt < 4; nt++)
            #pragma unroll
            for (int q = 0; q < 4; q++) acc[mt][nt][q] = 0.0f;

    // prologue: fill NSTAGE-1 stages
    #pragma unroll
    for (int c = 0; c < NSTAGE - 1; c++) {
        load_stage(a_s[c], b_s[c], rowBase, colBase, c * 64, tid);
        CP_COMMIT();
    }

    const uint32_t lrow = lane & 15;
    const uint32_t lkb = (lane >> 4) << 4;

    for (int c = 0; c < NCHUNK; c++) {
        CP_WAIT_1();
        __syncthreads();   // stage c ready; all warps done with stage c-1
        const int s = c % NSTAGE;

        if (c + NSTAGE - 1 < NCHUNK) {
            const int pf = c + NSTAGE - 1;
            load_stage(a_s[pf % NSTAGE], b_s[pf % NSTAGE], rowBase, colBase,
                       pf * 64, tid);
        }
        CP_COMMIT();

        const uint32_t a_cur = a_s[s], b_cur = b_s[s];
        #pragma unroll
        for (int ks = 0; ks < 4; ks++) {
            const uint32_t kb = ks * 32 + lkb;
            uint32_t af[4][4];
            #pragma unroll
            for (int mt = 0; mt < 4; mt++) {
                uint32_t row = warp_m + mt * 16 + lrow;
                ldsm_x4(af[mt][0], af[mt][1], af[mt][2], af[mt][3],
                        a_cur + SWZ128(row * 128 + kb));
            }
            uint32_t bf[4][2];
            #pragma unroll
            for (int nt2 = 0; nt2 < 2; nt2++) {
                uint32_t row = warp_n + nt2 * 16 + lrow;
                uint32_t m0, m1, m2, m3;
                ldsm_x4(m0, m1, m2, m3, b_cur + SWZ128(row * 128 + kb));
                bf[nt2 * 2 + 0][0] = m0; bf[nt2 * 2 + 0][1] = m2;
                bf[nt2 * 2 + 1][0] = m1; bf[nt2 * 2 + 1][1] = m3;
            }
            #pragma unroll
            for (int mt = 0; mt < 4; mt++)
                #pragma unroll
                for (int nt = 0; nt < 4; nt++)
                    mma_16816(acc[mt][nt], af[mt], bf[nt]);
        }
    }
    CP_WAIT_0();

    // ---- epilogue phase 1: e = exp(-sqrt(sq)), CTA-local row sums ----
    const int tgrp = lane >> 2;           // 0..7 (row within 8)
    const int tpair = (lane & 3) * 2;     // 0,2,4,6 (col pair)
    #pragma unroll
    for (int mt = 0; mt < 4; mt++) {
        const int m0 = rowBase + warp_m + mt * 16 + tgrp;
        const float x2a = __ldg(&g_x2[m0]);
        const float x2b = __ldg(&g_x2[m0 + 8]);
        float2 rsA = make_float2(0.0f, 0.0f);   // row tgrp
        float2 rsB = make_float2(0.0f, 0.0f);   // row tgrp+8
        #pragma unroll
        for (int nt = 0; nt < 4; nt++) {
            const int n = colBase + warp_n + nt * 8 + tpair;
            const float c2a = __ldg(&g_c2[n]);
            const float c2b = __ldg(&g_c2[n + 1]);
            float sq0 = fmaxf(x2a + c2a - 2.0f * acc[mt][nt][0], 0.0f);
            float sq1 = fmaxf(x2a + c2b - 2.0f * acc[mt][nt][1], 0.0f);
            float sq2 = fmaxf(x2b + c2a - 2.0f * acc[mt][nt][2], 0.0f);
            float sq3 = fmaxf(x2b + c2b - 2.0f * acc[mt][nt][3], 0.0f);
            float e0 = expf(-sqrtf(sq0));
            float e1 = expf(-sqrtf(sq1));
            float e2 = expf(-sqrtf(sq2));
            float e3 = expf(-sqrtf(sq3));
            acc[mt][nt][0] = e0; acc[mt][nt][1] = e1;
            acc[mt][nt][2] = e2; acc[mt][nt][3] = e3;
            rsA.x += e0 + e1;  rsA.y += e0 * sq0 + e1 * sq1;
            rsB.x += e2 + e3;  rsB.y += e2 * sq2 + e3 * sq3;
        }
        // reduce across the 4 lanes of the quad (same rows, different cols)
        #pragma unroll
        for (int m = 1; m <= 2; m <<= 1) {
            rsA.x += __shfl_xor_sync(0xFFFFFFFFu, rsA.x, m);
            rsA.y += __shfl_xor_sync(0xFFFFFFFFu, rsA.y, m);
            rsB.x += __shfl_xor_sync(0xFFFFFFFFu, rsB.x, m);
            rsB.y += __shfl_xor_sync(0xFFFFFFFFu, rsB.y, m);
        }
        if ((lane & 3) == 0) {
            const int rl = warp_m + mt * 16 + tgrp;
            atomicAdd(&srow[rl].x, rsA.x);
            atomicAdd(&srow[rl].y, rsA.y);
            atomicAdd(&srow[rl + 8].x, rsB.x);
            atomicAdd(&srow[rl + 8].y, rsB.y);
        }
    }
    __syncthreads();                 // srow complete for this CTA

    // ---- epilogue phase 2: cluster-wide row sums via DSMEM ----
    CLUSTER_ARRIVE();
    CLUSTER_WAIT();                  // all 8 CTAs' srow published
    if (tid < BMT) {
        const uint32_t myrow = smem_u32(&srow[tid]);
        float2 t = make_float2(0.0f, 0.0f);
        #pragma unroll
        for (uint32_t r = 0; r < CLUSTER_X; r++) {
            float2 v = ld_dsmem_f2(mapa_u32(myrow, r));
            t.x += v.x; t.y += v.y;
        }
        stot[tid] = t;
    }
    __syncthreads();                 // stot ready; this CTA's DSMEM reads done
    CLUSTER_ARRIVE();                // tell peers we no longer read their srow

    // ---- epilogue phase 3: write soft = e / sum_e (gmem only) ----
    #pragma unroll
    for (int mt = 0; mt < 4; mt++) {
        const int rl = warp_m + mt * 16 + tgrp;
        const int m0 = rowBase + rl;
        const float invA = 1.0f / stot[rl].x;
        const float invB = 1.0f / stot[rl + 8].x;
        #pragma unroll
        for (int nt = 0; nt < 4; nt++) {
            const int n = colBase + warp_n + nt * 8 + tpair;
            float2 v0, v1;
            v0.x = acc[mt][nt][0] * invA;
            v0.y = acc[mt][nt][1] * invA;
            v1.x = acc[mt][nt][2] * invB;
            v1.y = acc[mt][nt][3] * invB;
            *reinterpret_cast<float2*>(out + (size_t)m0 * K_DIM + n) = v0;
            *reinterpret_cast<float2*>(out + (size_t)(m0 + 8) * K_DIM + n) = v1;
        }
    }
    // rank 0 writes per-row loss partials: sum(soft*sq) = (sum e*sq)/(sum e)
    if (rank == 0 && tid < BMT)
        g_row_partial[rowBase + tid] = stot[tid].y / stot[tid].x;

    CLUSTER_WAIT();                  // don't exit while peers may read srow
}

// ---------------------------------------------------------------------------
// Kernel 3: deterministic reduction of row partials -> loss at out[last].
// ---------------------------------------------------------------------------
__global__ __launch_bounds__(1024) void loss_kernel(float* __restrict__ out,
                                                    long loss_idx) {
    __shared__ float s[1024];
    const int tid = threadIdx.x;
    float acc = 0.0f;
    for (int i = tid; i < R_TOTAL; i += 1024) acc += g_row_partial[i];
    s[tid] = acc;
    __syncthreads();
    #pragma unroll
    for (int stride = 512; stride > 0; stride >>= 1) {
        if (tid < stride) s[tid] += s[tid + stride];
        __syncthreads();
    }
    if (tid == 0) out[loss_idx] = s[0] / (float)B_DIM;
}

// ---------------------------------------------------------------------------
extern "C" void kernel_launch(void* const* d_in, const int* in_sizes, int n_in,
                              void* d_out, int out_size) {
    const float* X = (const float*)d_in[0];   // (16, 8192, 256) fp32
    const float* C = (const float*)d_in[1];   // (1024, 256) fp32
    float* out = (float*)d_out;               // soft (B,N,K) then loss scalar
    (void)in_sizes; (void)n_in;

    // 1) fp16 convert + norms
    {
        int total_warps = R_TOTAL + K_DIM;
        int blocks = (total_warps + 7) / 8;
        prepack_kernel<<<blocks, 256>>>(X, C);
    }
    // 2) fused sqdist + softmax (8-CTA clusters spanning K)
    {
        cudaFuncSetAttribute(fused_kernel,
                             cudaFuncAttributeMaxDynamicSharedMemorySize,
                             SMEM_DYN);
        dim3 grid(K_DIM / BNT, R_TOTAL / BMT);   // (8, 1024): 1024 clusters
        fused_kernel<<<grid, 256, SMEM_DYN>>>(out);
    }
    // 3) loss scalar
    {
        long loss_idx = (long)out_size - 1;
        loss_kernel<<<1, 1024>>>(out, loss_idx);
    }
}